// round 8
// baseline (speedup 1.0000x reference)
#include <cuda_runtime.h>
#include <math.h>

#define BATCH 64
#define NOBJ 16
#define NPRI 5460
#define NCLS 81
#define NCAND 49
#define NROWS (BATCH * NPRI)

#define STREAM_BLOCKS 1184
#define PATCH_BLOCKS  32
#define TOTAL_DONE    (STREAM_BLOCKS + PATCH_BLOCKS)
#define PLIST_CAP     (BATCH * NOBJ * NCAND)

// zero-initialized at module load; every launch leaves them zeroed (self-clean)
__device__ int      g_winner[NROWS];      // winner+1; 0 = background
__device__ int      g_plist[PLIST_CAP];   // packed (row<<5 | o) positive entries
__device__ int      g_plist_cnt;
__device__ double   g_conf;
__device__ double   g_loc;
__device__ int      g_cnt;
__device__ unsigned g_done;

// ---------------------------------------------------------------------------
// fast reciprocal: magic init + 2 Newton (rel err ~1.4e-6)
// ---------------------------------------------------------------------------
__device__ __forceinline__ float recip_fast(float v) {
    float y = __int_as_float(0x7EF311C3 - __float_as_int(v));
    y = y * (2.0f - v * y);
    y = y * (2.0f - v * y);
    return y;
}

// ---------------------------------------------------------------------------
// focal helpers — u = e^x formulation, base-2 log with folded ln2 constants.
//   sigma = u/(1+u), 1-sigma = 1/(1+u)
//   softplus(x) = ln2 * log2(1+u),  softplus(-x) = ln2 * (log2(1+u) - x*log2e)
// ---------------------------------------------------------------------------
#define LN2_F    0.6931471805599453f
#define LOG2E_F  1.4426950408889634f

__device__ __forceinline__ float focal_nt(float x) {
    const float u = __expf(x);             // MUFU EX2
    const float A = 1.0f + u;
    const float r = recip_fast(A);
    const float s = u * r;                 // sigmoid(x)
    const float L2 = __log2f(A);           // MUFU LG2
    return (0.75f * LN2_F) * (s * s) * L2;
}
__device__ __forceinline__ float focal_t(float x) {
    const float u = __expf(x);
    const float A = 1.0f + u;
    const float r = recip_fast(A);         // 1 - sigmoid(x)
    const float L2 = __log2f(A);
    return (0.25f * LN2_F) * (r * r) * (L2 - x * LOG2E_F);
}

__device__ __forceinline__ float warp_sum(float v) {
#pragma unroll
    for (int off = 16; off; off >>= 1) v += __shfl_xor_sync(0xffffffffu, v, off);
    return v;
}

// shared tail: block-reduce sum into g_conf, then last-block-done finalize
__device__ __forceinline__ void reduce_and_finalize(float sum, float* out) {
    __shared__ float ws[8];
    __shared__ bool  isLast;
    const int lane = threadIdx.x & 31;
    const int wid  = threadIdx.x >> 5;
#pragma unroll
    for (int off = 16; off; off >>= 1) sum += __shfl_down_sync(0xffffffffu, sum, off);
    if (lane == 0) ws[wid] = sum;
    __syncthreads();
    if (wid == 0) {
        sum = (lane < 8) ? ws[lane] : 0.0f;
#pragma unroll
        for (int off = 4; off; off >>= 1) sum += __shfl_down_sync(0xffffffffu, sum, off);
        if (lane == 0) {
            atomicAdd(&g_conf, (double)sum);
            __threadfence();
            const unsigned t = atomicAdd(&g_done, 1u);
            isLast = (t == TOTAL_DONE - 1);
        }
    }
    __syncthreads();
    if (isLast && threadIdx.x == 0) {
        __threadfence();
        const double conf = g_conf / (double)NROWS;
        const double loc  = g_loc / fmax((double)g_cnt, 1.0);
        out[0] = (float)(conf + loc);
        g_conf = 0.0; g_loc = 0.0; g_cnt = 0; g_done = 0u; g_plist_cnt = 0;
    }
}

// ---------------------------------------------------------------------------
// Kernel 1: ATSS assignment — one WARP per (image, object). Analytic grid
// priors; top-9 per level lie in the clamped 5x5 window around nearest cell.
// ---------------------------------------------------------------------------
__global__ void assign_kernel(const float* __restrict__ locs,
                              const float* __restrict__ boxes) {
    __shared__ int   s_cand[4][NCAND];
    __shared__ int   s_aux [4][NCAND];
    __shared__ float s_pov [4][NCAND];

    const int wl    = threadIdx.x >> 5;
    const int lane  = threadIdx.x & 31;
    const int wglob = blockIdx.x * 4 + wl;
    const int b     = wglob >> 4;
    const int o     = wglob & 15;

    const float4 bb = __ldg(reinterpret_cast<const float4*>(boxes) + (b * NOBJ + o));
    const float bx1 = bb.x, by1 = bb.y, bx2 = bb.z, by2 = bb.w;
    const float bcx = (bx1 + bx2) * 0.5f;
    const float bcy = (by1 + by2) * 0.5f;
    const float area_a = (bx2 - bx1) * (by2 - by1);

    const float FINF = __int_as_float(0x7f800000);
    const int fms[6]   = {64, 32, 16, 8, 4, 2};
    const int bases[6] = {0, 4096, 5120, 5376, 5440, 5456};

    int slot = 0;
#pragma unroll
    for (int l = 0; l < 6; l++) {
        const int fm   = fms[l];
        const int base = bases[l];
        const int w    = (fm < 5) ? fm : 5;
        const int nc   = w * w;
        const int k    = (fm * fm < 9) ? fm * fm : 9;

        int ic = (int)(bcx * (float)fm); ic = min(max(ic, 0), fm - 1);
        int jc = (int)(bcy * (float)fm); jc = min(max(jc, 0), fm - 1);
        const int lox = min(max(ic - 2, 0), fm - w);
        const int loy = min(max(jc - 2, 0), fm - w);

        float d    = FINF;
        int   pidx = 0x7fffffff;
        int   ix = 0, iy = 0;
        if (lane < nc) {
            const int ux = lane % w, uy = lane / w;
            ix = lox + ux; iy = loy + uy;
            const float pcx = ((float)ix + 0.5f) / (float)fm;
            const float pcy = ((float)iy + 0.5f) / (float)fm;
            const float dx = bcx - pcx, dy = bcy - pcy;
            d    = sqrtf(dx * dx + dy * dy);
            pidx = iy * fm + ix;
        }

        int rank = 0;
#pragma unroll
        for (int j = 0; j < nc; j++) {
            const float dj = __shfl_sync(0xffffffffu, d, j);
            const int   pj = __shfl_sync(0xffffffffu, pidx, j);
            rank += (dj < d) | ((dj == d) & (pj < pidx));
        }
        if (lane < nc && rank < k) {
            s_cand[wl][slot + rank] = base + pidx;
            s_aux [wl][slot + rank] = (fm << 20) | (iy << 10) | ix;
        }
        slot += k;
    }
    __syncwarp();

#pragma unroll
    for (int pass = 0; pass < 2; pass++) {
        const int c = lane + pass * 32;
        if (c < NCAND) {
            const int aux = s_aux[wl][c];
            const int fm  = aux >> 20;
            const int iy  = (aux >> 10) & 1023, ix = aux & 1023;
            const float pcx = ((float)ix + 0.5f) / (float)fm;
            const float pcy = ((float)iy + 0.5f) / (float)fm;
            const float pwh = 1.5f / (float)fm;
            const float px1 = pcx - pwh * 0.5f, py1 = pcy - pwh * 0.5f;
            const float px2 = pcx + pwh * 0.5f, py2 = pcy + pwh * 0.5f;
            const float tlx = fmaxf(bx1, px1), tly = fmaxf(by1, py1);
            const float brx = fminf(bx2, px2), bry = fminf(by2, py2);
            const float inter = fmaxf(brx - tlx, 0.0f) * fmaxf(bry - tly, 0.0f);
            const float area_b = (px2 - px1) * (py2 - py1);
            s_pov[wl][c] = inter / (area_a + area_b - inter + 1e-10f);
        }
    }
    __syncwarp();

    float p0 = (lane < NCAND) ? s_pov[wl][lane] : 0.0f;
    float p1 = (lane + 32 < NCAND) ? s_pov[wl][lane + 32] : 0.0f;
    const float mean = warp_sum(p0 + p1) / 49.0f;
    float d0 = (lane < NCAND) ? (p0 - mean) : 0.0f;
    float d1 = (lane + 32 < NCAND) ? (p1 - mean) : 0.0f;
    const float ss = warp_sum(d0 * d0 + d1 * d1);
    const float thresh = mean + sqrtf(ss / 48.0f);

    float lloc = 0.0f;
    int   lcnt = 0;
#pragma unroll
    for (int pass = 0; pass < 2; pass++) {
        const int c = lane + pass * 32;
        if (c < NCAND) {
            const int aux = s_aux[wl][c];
            const int fm  = aux >> 20;
            const int iy  = (aux >> 10) & 1023, ix = aux & 1023;
            const float pcx = ((float)ix + 0.5f) / (float)fm;
            const float pcy = ((float)iy + 0.5f) / (float)fm;
            const float pwh = 1.5f / (float)fm;
            const bool inside = (bx1 <= pcx) && (pcx <= bx2) && (by1 <= pcy) && (pcy <= by2);
            if (inside && (s_pov[wl][c] > thresh)) {
                const int g   = s_cand[wl][c];
                const int row = b * NPRI + g;
                atomicMax(&g_winner[row], o + 1);
                const int pos = atomicAdd(&g_plist_cnt, 1);
                g_plist[pos] = (row << 5) | o;
                const float4 gl = __ldg(reinterpret_cast<const float4*>(locs) + ((size_t)b * NPRI + g));
                const float dcx = (gl.x * pwh) / 10.0f + pcx;
                const float dcy = (gl.y * pwh) / 10.0f + pcy;
                const float dw  = expf(gl.z / 5.0f) * pwh;
                const float dh  = expf(gl.w / 5.0f) * pwh;
                const float px1 = dcx - dw * 0.5f, py1 = dcy - dh * 0.5f;
                const float px2 = dcx + dw * 0.5f, py2 = dcy + dh * 0.5f;
                const float tlx = fmaxf(px1, bx1), tly = fmaxf(py1, by1);
                const float brx = fminf(px2, bx2), bry = fminf(py2, by2);
                const float inter = fmaxf(brx - tlx, 0.0f) * fmaxf(bry - tly, 0.0f);
                const float ap = fmaxf(px2 - px1, 0.0f) * fmaxf(py2 - py1, 0.0f);
                const float iou = inter / (ap + area_a - inter + 1e-7f);
                const float cpx = (px1 + px2) * 0.5f, cpy = (py1 + py2) * 0.5f;
                const float ddx = cpx - bcx, ddy = cpy - bcy;
                const float d2 = ddx * ddx + ddy * ddy;
                const float etlx = fminf(px1, bx1), etly = fminf(py1, by1);
                const float ebrx = fmaxf(px2, bx2), ebry = fmaxf(py2, by2);
                const float ex = ebrx - etlx, ey = ebry - etly;
                const float diag2 = ex * ex + ey * ey + 1e-7f;
                lloc += 1.0f - iou + d2 / diag2;
                lcnt += 1;
            }
        }
    }
#pragma unroll
    for (int off = 16; off; off >>= 1) {
        lloc += __shfl_down_sync(0xffffffffu, lloc, off);
        lcnt += __shfl_down_sync(0xffffffffu, lcnt, off);
    }
    if (lane == 0 && lcnt > 0) {
        atomicAdd(&g_loc, (double)lloc);
        atomicAdd(&g_cnt, lcnt);
    }
}

// ---------------------------------------------------------------------------
// Kernel 2: streaming focal. Every element as non-target, EXCEPT each row's
// class-0 element gets the target term inline (background default). At most
// one row-start per 8-elem chunk since NCLS=81 > 8.
// ---------------------------------------------------------------------------
__global__ void stream_kernel(const float* __restrict__ scores, float* __restrict__ out) {
    const int total = NROWS * NCLS;           // 28,304,640, divisible by 8
    const int nthr  = gridDim.x * blockDim.x;
    float s0 = 0.0f, s1 = 0.0f;
    for (int i = (blockIdx.x * blockDim.x + threadIdx.x) * 8; i < total; i += nthr * 8) {
        const float4 a = *reinterpret_cast<const float4*>(scores + i);
        const float4 c = *reinterpret_cast<const float4*>(scores + i + 4);
        s0 += focal_nt(a.x); s1 += focal_nt(a.y);
        s0 += focal_nt(a.z); s1 += focal_nt(a.w);
        s0 += focal_nt(c.x); s1 += focal_nt(c.y);
        s0 += focal_nt(c.z); s1 += focal_nt(c.w);
        // row-start (class 0) element in this chunk, if any
        const unsigned q  = (unsigned)i % 81u;
        const unsigned j0 = (81u - q) % 81u;
        if (j0 < 8u) {
            float xv = a.x;
            xv = (j0 == 1u) ? a.y : xv;
            xv = (j0 == 2u) ? a.z : xv;
            xv = (j0 == 3u) ? a.w : xv;
            xv = (j0 == 4u) ? c.x : xv;
            xv = (j0 == 5u) ? c.y : xv;
            xv = (j0 == 6u) ? c.z : xv;
            xv = (j0 == 7u) ? c.w : xv;
            s0 += focal_t(xv) - focal_nt(xv);
        }
    }
    reduce_and_finalize(s0 + s1, out);
}

// ---------------------------------------------------------------------------
// Kernel 3: patch positives — winner entries swap the target column from
// class 0 to the winning label. Self-cleans g_winner.
// ---------------------------------------------------------------------------
__global__ void patch_kernel(const float* __restrict__ scores,
                             const int* __restrict__ labels,
                             float* __restrict__ out) {
    const int n    = g_plist_cnt;
    const int nthr = gridDim.x * blockDim.x;
    float v = 0.0f;
    for (int idx = blockIdx.x * blockDim.x + threadIdx.x; idx < n; idx += nthr) {
        const int e   = g_plist[idx];
        const int row = e >> 5;
        const int o   = e & 31;
        if (g_winner[row] == o + 1) {            // this entry is the winner
            g_winner[row] = 0;                   // self-clean
            const int cls = __ldg(&labels[(row / NPRI) * NOBJ + o]);
            const float x_c = __ldg(scores + (size_t)row * NCLS + cls);
            const float x_0 = __ldg(scores + (size_t)row * NCLS);
            v += (focal_t(x_c) - focal_nt(x_c)) - (focal_t(x_0) - focal_nt(x_0));
        }
    }
    reduce_and_finalize(v, out);
}

// ---------------------------------------------------------------------------
extern "C" void kernel_launch(void* const* d_in, const int* in_sizes, int n_in,
                              void* d_out, int out_size) {
    const float* locs   = (const float*)d_in[0];
    const float* scores = (const float*)d_in[1];
    const float* boxes  = (const float*)d_in[2];
    const int*   labels = (const int*)d_in[3];

    // one-time host-side resources (no device memory involved)
    static cudaStream_t s_aux = nullptr;
    static cudaEvent_t  ev_fork = nullptr, ev_join = nullptr;
    if (s_aux == nullptr) {
        cudaStreamCreateWithFlags(&s_aux, cudaStreamNonBlocking);
        cudaEventCreateWithFlags(&ev_fork, cudaEventDisableTiming);
        cudaEventCreateWithFlags(&ev_join, cudaEventDisableTiming);
    }

    // fork: aux stream runs assign -> patch, overlapping the stream kernel.
    // Finalization is a shared last-block-done over stream + patch blocks.
    cudaEventRecord(ev_fork, 0);
    cudaStreamWaitEvent(s_aux, ev_fork, 0);
    assign_kernel<<<256, 128, 0, s_aux>>>(locs, boxes);
    patch_kernel<<<PATCH_BLOCKS, 256, 0, s_aux>>>(scores, labels, (float*)d_out);
    cudaEventRecord(ev_join, s_aux);

    stream_kernel<<<STREAM_BLOCKS, 256>>>(scores, (float*)d_out);

    // join aux back into the origin stream (required for graph capture)
    cudaStreamWaitEvent(0, ev_join, 0);
}

// round 9
// speedup vs baseline: 1.0069x; 1.0069x over previous
#include <cuda_runtime.h>
#include <math.h>

#define BATCH 64
#define NOBJ 16
#define NPRI 5460
#define NCLS 81
#define NCAND 49
#define NROWS (BATCH * NPRI)

#define STREAM_BLOCKS 1184
#define AUX_BLOCKS    256
#define ASSIGN_BLOCKS 128        // blocks 0..127 carry the 1024 (b,o) warps
#define TOTAL_DONE    (STREAM_BLOCKS + AUX_BLOCKS)

// zero-initialized at module load; every launch leaves them zeroed (self-clean)
__device__ int      g_winner[NROWS];   // winner+1; 0 = background
__device__ double   g_conf;
__device__ double   g_loc;
__device__ int      g_cnt;
__device__ unsigned g_done;
__device__ unsigned g_abar;            // assign-phase barrier counter

// ---------------------------------------------------------------------------
// fast reciprocal: magic init + 2 Newton (rel err ~1.4e-6)
// ---------------------------------------------------------------------------
__device__ __forceinline__ float recip_fast(float v) {
    float y = __int_as_float(0x7EF311C3 - __float_as_int(v));
    y = y * (2.0f - v * y);
    y = y * (2.0f - v * y);
    return y;
}

// ---------------------------------------------------------------------------
// focal helpers — u = e^x formulation (branch-free), base-2 log fold.
// ---------------------------------------------------------------------------
#define LN2_F    0.6931471805599453f
#define LOG2E_F  1.4426950408889634f

__device__ __forceinline__ float focal_nt(float x) {
    const float u = __expf(x);             // MUFU EX2
    const float A = 1.0f + u;
    const float r = recip_fast(A);
    const float s = u * r;                 // sigmoid(x)
    const float L2 = __log2f(A);           // MUFU LG2
    return (0.75f * LN2_F) * (s * s) * L2;
}
__device__ __forceinline__ float focal_t(float x) {
    const float u = __expf(x);
    const float A = 1.0f + u;
    const float r = recip_fast(A);         // 1 - sigmoid(x)
    const float L2 = __log2f(A);
    return (0.25f * LN2_F) * (r * r) * (L2 - x * LOG2E_F);
}

__device__ __forceinline__ float warp_sum(float v) {
#pragma unroll
    for (int off = 16; off; off >>= 1) v += __shfl_xor_sync(0xffffffffu, v, off);
    return v;
}

// shared tail: block-reduce sum into g_conf, then last-block-done finalize
__device__ __forceinline__ void reduce_and_finalize(float sum, float* out) {
    __shared__ float ws[8];
    __shared__ bool  isLast;
    const int lane = threadIdx.x & 31;
    const int wid  = threadIdx.x >> 5;
#pragma unroll
    for (int off = 16; off; off >>= 1) sum += __shfl_down_sync(0xffffffffu, sum, off);
    if (lane == 0) ws[wid] = sum;
    __syncthreads();
    if (wid == 0) {
        sum = (lane < 8) ? ws[lane] : 0.0f;
#pragma unroll
        for (int off = 4; off; off >>= 1) sum += __shfl_down_sync(0xffffffffu, sum, off);
        if (lane == 0) {
            atomicAdd(&g_conf, (double)sum);
            __threadfence();
            const unsigned t = atomicAdd(&g_done, 1u);
            isLast = (t == TOTAL_DONE - 1);
        }
    }
    __syncthreads();
    if (isLast && threadIdx.x == 0) {
        __threadfence();
        const double conf = g_conf / (double)NROWS;
        const double loc  = g_loc / fmax((double)g_cnt, 1.0);
        out[0] = (float)(conf + loc);
        g_conf = 0.0; g_loc = 0.0; g_cnt = 0; g_done = 0u; g_abar = 0u;
    }
}

// ---------------------------------------------------------------------------
// Kernel 1 (aux stream): two phases in one kernel.
//   Phase A (blocks 0..127, 8 warps each = 1024 (image,object) warps):
//     ATSS assignment on the analytic prior grid + DIoU accumulation.
//   Phase barrier: atomic counter (all 256 blocks are resident -> safe spin).
//   Phase B (all 256 blocks): per-row focal correction + g_winner self-clean.
// ---------------------------------------------------------------------------
__global__ void __launch_bounds__(256) aux_kernel(
        const float* __restrict__ locs,
        const float* __restrict__ boxes,
        const float* __restrict__ scores,
        const int*   __restrict__ labels,
        float* __restrict__ out) {
    __shared__ int   s_cand[8][NCAND];
    __shared__ int   s_aux [8][NCAND];
    __shared__ float s_pov [8][NCAND];

    const int wl   = threadIdx.x >> 5;     // 0..7
    const int lane = threadIdx.x & 31;

    // ---------------- Phase A: assignment ----------------
    if (blockIdx.x < ASSIGN_BLOCKS) {
        const int wglob = blockIdx.x * 8 + wl;     // 0..1023
        const int b     = wglob >> 4;
        const int o     = wglob & 15;

        const float4 bb = __ldg(reinterpret_cast<const float4*>(boxes) + (b * NOBJ + o));
        const float bx1 = bb.x, by1 = bb.y, bx2 = bb.z, by2 = bb.w;
        const float bcx = (bx1 + bx2) * 0.5f;
        const float bcy = (by1 + by2) * 0.5f;
        const float area_a = (bx2 - bx1) * (by2 - by1);

        const float FINF = __int_as_float(0x7f800000);
        const int fms[6]   = {64, 32, 16, 8, 4, 2};
        const int bases[6] = {0, 4096, 5120, 5376, 5440, 5456};

        int slot = 0;
#pragma unroll
        for (int l = 0; l < 6; l++) {
            const int fm   = fms[l];
            const int base = bases[l];
            const int w    = (fm < 5) ? fm : 5;
            const int nc   = w * w;
            const int k    = (fm * fm < 9) ? fm * fm : 9;

            int ic = (int)(bcx * (float)fm); ic = min(max(ic, 0), fm - 1);
            int jc = (int)(bcy * (float)fm); jc = min(max(jc, 0), fm - 1);
            const int lox = min(max(ic - 2, 0), fm - w);
            const int loy = min(max(jc - 2, 0), fm - w);

            float d    = FINF;
            int   pidx = 0x7fffffff;
            int   ix = 0, iy = 0;
            if (lane < nc) {
                const int ux = lane % w, uy = lane / w;
                ix = lox + ux; iy = loy + uy;
                const float pcx = ((float)ix + 0.5f) / (float)fm;
                const float pcy = ((float)iy + 0.5f) / (float)fm;
                const float dx = bcx - pcx, dy = bcy - pcy;
                d    = sqrtf(dx * dx + dy * dy);
                pidx = iy * fm + ix;
            }

            int rank = 0;
#pragma unroll
            for (int j = 0; j < nc; j++) {
                const float dj = __shfl_sync(0xffffffffu, d, j);
                const int   pj = __shfl_sync(0xffffffffu, pidx, j);
                rank += (dj < d) | ((dj == d) & (pj < pidx));
            }
            if (lane < nc && rank < k) {
                s_cand[wl][slot + rank] = base + pidx;
                s_aux [wl][slot + rank] = (fm << 20) | (iy << 10) | ix;
            }
            slot += k;
        }
        __syncwarp();

#pragma unroll
        for (int pass = 0; pass < 2; pass++) {
            const int c = lane + pass * 32;
            if (c < NCAND) {
                const int aux = s_aux[wl][c];
                const int fm  = aux >> 20;
                const int iy  = (aux >> 10) & 1023, ix = aux & 1023;
                const float pcx = ((float)ix + 0.5f) / (float)fm;
                const float pcy = ((float)iy + 0.5f) / (float)fm;
                const float pwh = 1.5f / (float)fm;
                const float px1 = pcx - pwh * 0.5f, py1 = pcy - pwh * 0.5f;
                const float px2 = pcx + pwh * 0.5f, py2 = pcy + pwh * 0.5f;
                const float tlx = fmaxf(bx1, px1), tly = fmaxf(by1, py1);
                const float brx = fminf(bx2, px2), bry = fminf(by2, py2);
                const float inter = fmaxf(brx - tlx, 0.0f) * fmaxf(bry - tly, 0.0f);
                const float area_b = (px2 - px1) * (py2 - py1);
                s_pov[wl][c] = inter / (area_a + area_b - inter + 1e-10f);
            }
        }
        __syncwarp();

        float p0 = (lane < NCAND) ? s_pov[wl][lane] : 0.0f;
        float p1 = (lane + 32 < NCAND) ? s_pov[wl][lane + 32] : 0.0f;
        const float mean = warp_sum(p0 + p1) / 49.0f;
        float d0 = (lane < NCAND) ? (p0 - mean) : 0.0f;
        float d1 = (lane + 32 < NCAND) ? (p1 - mean) : 0.0f;
        const float ss = warp_sum(d0 * d0 + d1 * d1);
        const float thresh = mean + sqrtf(ss / 48.0f);

        float lloc = 0.0f;
        int   lcnt = 0;
#pragma unroll
        for (int pass = 0; pass < 2; pass++) {
            const int c = lane + pass * 32;
            if (c < NCAND) {
                const int aux = s_aux[wl][c];
                const int fm  = aux >> 20;
                const int iy  = (aux >> 10) & 1023, ix = aux & 1023;
                const float pcx = ((float)ix + 0.5f) / (float)fm;
                const float pcy = ((float)iy + 0.5f) / (float)fm;
                const float pwh = 1.5f / (float)fm;
                const bool inside = (bx1 <= pcx) && (pcx <= bx2) && (by1 <= pcy) && (pcy <= by2);
                if (inside && (s_pov[wl][c] > thresh)) {
                    const int g = s_cand[wl][c];
                    atomicMax(&g_winner[b * NPRI + g], o + 1);
                    const float4 gl = __ldg(reinterpret_cast<const float4*>(locs) + ((size_t)b * NPRI + g));
                    const float dcx = (gl.x * pwh) / 10.0f + pcx;
                    const float dcy = (gl.y * pwh) / 10.0f + pcy;
                    const float dw  = expf(gl.z / 5.0f) * pwh;
                    const float dh  = expf(gl.w / 5.0f) * pwh;
                    const float px1 = dcx - dw * 0.5f, py1 = dcy - dh * 0.5f;
                    const float px2 = dcx + dw * 0.5f, py2 = dcy + dh * 0.5f;
                    const float tlx = fmaxf(px1, bx1), tly = fmaxf(py1, by1);
                    const float brx = fminf(px2, bx2), bry = fminf(py2, by2);
                    const float inter = fmaxf(brx - tlx, 0.0f) * fmaxf(bry - tly, 0.0f);
                    const float ap = fmaxf(px2 - px1, 0.0f) * fmaxf(py2 - py1, 0.0f);
                    const float iou = inter / (ap + area_a - inter + 1e-7f);
                    const float cpx = (px1 + px2) * 0.5f, cpy = (py1 + py2) * 0.5f;
                    const float ddx = cpx - bcx, ddy = cpy - bcy;
                    const float d2 = ddx * ddx + ddy * ddy;
                    const float etlx = fminf(px1, bx1), etly = fminf(py1, by1);
                    const float ebrx = fmaxf(px2, bx2), ebry = fmaxf(py2, by2);
                    const float ex = ebrx - etlx, ey = ebry - etly;
                    const float diag2 = ex * ex + ey * ey + 1e-7f;
                    lloc += 1.0f - iou + d2 / diag2;
                    lcnt += 1;
                }
            }
        }
#pragma unroll
        for (int off = 16; off; off >>= 1) {
            lloc += __shfl_down_sync(0xffffffffu, lloc, off);
            lcnt += __shfl_down_sync(0xffffffffu, lcnt, off);
        }
        if (lane == 0 && lcnt > 0) {
            atomicAdd(&g_loc, (double)lloc);
            atomicAdd(&g_cnt, lcnt);
        }
    }

    // ---------------- Phase barrier ----------------
    __syncthreads();
    if (threadIdx.x == 0) {
        if (blockIdx.x < ASSIGN_BLOCKS) {
            __threadfence();
            atomicAdd(&g_abar, 1u);
        }
        while (atomicAdd(&g_abar, 0u) < ASSIGN_BLOCKS) __nanosleep(64);
    }
    __syncthreads();
    __threadfence();

    // ---------------- Phase B: correction ----------------
    const int nthr = AUX_BLOCKS * 256;
    float v = 0.0f;
    for (int row = blockIdx.x * 256 + threadIdx.x; row < NROWS; row += nthr) {
        const int w = g_winner[row];
        g_winner[row] = 0;                       // self-clean for next replay
        const int cls = (w > 0) ? __ldg(&labels[(row / NPRI) * NOBJ + (w - 1)]) : 0;
        const float x = __ldg(scores + (size_t)row * NCLS + cls);
        v += focal_t(x) - focal_nt(x);
    }
    reduce_and_finalize(v, out);
}

// ---------------------------------------------------------------------------
// Kernel 2 (main stream): streaming focal — every element as non-target.
// ---------------------------------------------------------------------------
__global__ void stream_kernel(const float* __restrict__ scores, float* __restrict__ out) {
    const int total = NROWS * NCLS;           // 28,304,640, divisible by 8
    const int nthr  = gridDim.x * blockDim.x;
    float s0 = 0.0f, s1 = 0.0f;
    for (int i = (blockIdx.x * blockDim.x + threadIdx.x) * 8; i < total; i += nthr * 8) {
        const float4 a = *reinterpret_cast<const float4*>(scores + i);
        const float4 c = *reinterpret_cast<const float4*>(scores + i + 4);
        s0 += focal_nt(a.x); s1 += focal_nt(a.y);
        s0 += focal_nt(a.z); s1 += focal_nt(a.w);
        s0 += focal_nt(c.x); s1 += focal_nt(c.y);
        s0 += focal_nt(c.z); s1 += focal_nt(c.w);
    }
    reduce_and_finalize(s0 + s1, out);
}

// ---------------------------------------------------------------------------
extern "C" void kernel_launch(void* const* d_in, const int* in_sizes, int n_in,
                              void* d_out, int out_size) {
    const float* locs   = (const float*)d_in[0];
    const float* scores = (const float*)d_in[1];
    const float* boxes  = (const float*)d_in[2];
    const int*   labels = (const int*)d_in[3];

    // one-time host-side resources (no device memory involved)
    static cudaStream_t s_aux = nullptr;
    static cudaEvent_t  ev_fork = nullptr, ev_join = nullptr;
    if (s_aux == nullptr) {
        cudaStreamCreateWithFlags(&s_aux, cudaStreamNonBlocking);
        cudaEventCreateWithFlags(&ev_fork, cudaEventDisableTiming);
        cudaEventCreateWithFlags(&ev_join, cudaEventDisableTiming);
    }

    // fork: aux stream runs the two-phase assign+corr kernel, overlapping the
    // stream kernel. Finalization is a shared last-block-done over both.
    cudaEventRecord(ev_fork, 0);
    cudaStreamWaitEvent(s_aux, ev_fork, 0);
    aux_kernel<<<AUX_BLOCKS, 256, 0, s_aux>>>(locs, boxes, scores, labels, (float*)d_out);
    cudaEventRecord(ev_join, s_aux);

    stream_kernel<<<STREAM_BLOCKS, 256>>>(scores, (float*)d_out);

    // join aux back into the origin stream (required for graph capture)
    cudaStreamWaitEvent(0, ev_join, 0);
}